// round 15
// baseline (speedup 1.0000x reference)
#include <cuda_runtime.h>
#include <cuda_bf16.h>
#include <cstdint>
#include <math.h>

#define S   2048
#define H   2048
#define ROOM 256
#define NH  16
#define HD  128
#define SCALE 0.08838834764831845f  // 1/sqrt(128)

typedef __nv_bfloat16 bf16;

// ---------------- device globals (allocation-free scratch) ----------------
__device__ __align__(16) bf16 g_Hh [(size_t)S*H],    g_Hl [(size_t)S*H];     // hidden planes
__device__ __align__(16) bf16 g_QBh[(size_t)H*H],    g_QBl[(size_t)H*H];     // q_block planes
__device__ __align__(16) bf16 g_KBh[(size_t)ROOM*H], g_KBl[(size_t)ROOM*H];  // k_block planes
__device__ __align__(16) bf16 g_VBh[(size_t)ROOM*H], g_VBl[(size_t)ROOM*H];  // v_block planes
__device__ __align__(16) bf16 g_OBth[(size_t)H*H],   g_OBtl[(size_t)H*H];    // o_active^T [n][t]
__device__ __align__(16) bf16 g_Qh [(size_t)S*H],    g_Ql [(size_t)S*H];     // Q projection planes
__device__ __align__(16) bf16 g_Kh [(size_t)S*ROOM], g_Kl [(size_t)S*ROOM];  // k_one planes
__device__ __align__(16) bf16 g_Vth[(size_t)ROOM*S], g_Vtl[(size_t)ROOM*S];  // v_one^T [d][s]
__device__ __align__(16) bf16 g_Wh [(size_t)NH*S*S], g_Wl [(size_t)NH*S*S];  // softmaxed W planes
__device__ __align__(16) bf16 g_Ah [(size_t)S*H],    g_Al [(size_t)S*H];     // attn_out planes
__device__ int g_rooms[8];

// ---------------- helpers ----------------
__device__ __forceinline__ uint32_t smem_u32(const void* p) {
    uint32_t a;
    asm("{ .reg .u64 t; cvta.to.shared.u64 t, %1; cvt.u32.u64 %0, t; }" : "=r"(a) : "l"(p));
    return a;
}
__device__ __forceinline__ void split1(float x, bf16& h, bf16& l) {
    h = __float2bfloat16_rn(x);
    l = __float2bfloat16_rn(x - __bfloat162float(h));
}
__device__ __forceinline__ unsigned pack2(bf16 a, bf16 b) {
    return ((unsigned)__bfloat16_as_ushort(b) << 16) | __bfloat16_as_ushort(a);
}
__device__ __forceinline__ void mma16816(float* d, const unsigned* a, const unsigned* b)
{
    asm volatile(
        "mma.sync.aligned.m16n8k16.row.col.f32.bf16.bf16.f32 "
        "{%0,%1,%2,%3}, {%4,%5,%6,%7}, {%8,%9}, {%0,%1,%2,%3};\n"
        : "+f"(d[0]), "+f"(d[1]), "+f"(d[2]), "+f"(d[3])
        : "r"(a[0]), "r"(a[1]), "r"(a[2]), "r"(a[3]), "r"(b[0]), "r"(b[1]));
}
__device__ __forceinline__ void ldm_x4(unsigned &r0, unsigned &r1, unsigned &r2, unsigned &r3,
                                       uint32_t addr)
{
    asm volatile("ldmatrix.sync.aligned.m8n8.x4.shared.b16 {%0,%1,%2,%3}, [%4];"
                 : "=r"(r0), "=r"(r1), "=r"(r2), "=r"(r3) : "r"(addr));
}
__device__ __forceinline__ void cpasync16(uint32_t dst, const void* src) {
    asm volatile("cp.async.cg.shared.global [%0], [%1], 16;" :: "r"(dst), "l"(src) : "memory");
}

// ---------------------------------------------------------------------------
// cp.async + ldmatrix NT GEMM core — 256 threads, 8 warps (2m x 4n of 64x32).
// C[128,128] = A[M,K] @ B[N,K]^T, 3-term split (hh+hl+lh), fp32 accum.
// BK=32, double-buffered, smem 64KB, 2 CTAs/SM.
// Staging: per thread plane=(tid>>2)&1, k8=tid&3, r0=tid>>3 (0..31);
// rows r0+32i (i<4) for A and B (8 cp.async/thread/chunk). Swizzle
// u' = u ^ (row&7) — invariant under +32 rows.
// ---------------------------------------------------------------------------
#define DSMEM (2 * 32768)

template<bool GATHER, bool SPLITOUT>
__device__ __forceinline__ void gemm_core(
    const bf16* __restrict__ Ah_, const bf16* __restrict__ Al_, int lda,
    const bf16* __restrict__ Bh_, const bf16* __restrict__ Bl_, int ldb,
    int nch, int m0, int n0, float scale,
    float* __restrict__ Cf, bf16* __restrict__ Ch, bf16* __restrict__ Cl, int ldc)
{
    extern __shared__ char smemraw[];
    const uint32_t sbase = smem_u32(smemraw);
    const int tid = threadIdx.x;          // 0..255
    const int l = tid & 31, w = tid >> 5; // 8 warps
    const int wm = w >> 2, wn = w & 3;    // 2 x 4 of 64x32

    const int plane = (tid >> 2) & 1;
    const int k8    = tid & 3;
    const int r0    = tid >> 3;                   // 0..31
    const int swu   = (tid & 7) ^ (r0 & 7);
    const bf16* Asrc = (plane ? Al_ : Ah_) + (size_t)(m0 + r0) * lda + k8 * 8;
    int brow = n0 + r0;
    if (GATHER) brow = g_rooms[n0 >> 8] * ROOM + ((n0 + r0) & 255);
    const bf16* Bsrc = (plane ? Bl_ : Bh_) + (size_t)brow * ldb + k8 * 8;
    const uint32_t dA0 = sbase + r0 * 128 + swu * 16;
    const uint32_t dB0 = dA0 + 16384;

    auto stage = [&](int kk, int buf) {
        const uint32_t boff = buf * 32768;
        const bf16* as = Asrc + kk;
        const bf16* bs = Bsrc + kk;
#pragma unroll
        for (int i = 0; i < 4; i++) {
            cpasync16(dA0 + boff + i * 4096, as + (size_t)i * 32 * lda);
            cpasync16(dB0 + boff + i * 4096, bs + (size_t)i * 32 * ldb);
        }
        asm volatile("cp.async.commit_group;" ::: "memory");
    };

    float acc[4][4][4];
#pragma unroll
    for (int i = 0; i < 4; i++)
#pragma unroll
        for (int j = 0; j < 4; j++)
#pragma unroll
            for (int r = 0; r < 4; r++) acc[i][j][r] = 0.f;

    stage(0, 0);
    stage(32, 1);

    for (int c = 0; c < nch; c++) {
        if (c + 1 < nch) asm volatile("cp.async.wait_group 1;" ::: "memory");
        else             asm volatile("cp.async.wait_group 0;" ::: "memory");
        __syncthreads();
        const uint32_t Ab = sbase + (c & 1) * 32768;
        const uint32_t Bb = Ab + 16384;
        const int mi = l >> 3;
        const int r8 = l & 7;

#pragma unroll
        for (int ks = 0; ks < 2; ks++) {
            // B fragments: 4 n8-blocks (warp n=32), hi+lo
            unsigned bh[4][2], bl[4][2];
#pragma unroll
            for (int jp = 0; jp < 2; jp++) {
                int nl = wn * 32 + jp * 16 + (mi >> 1) * 8 + r8;
                int uh = (    ks * 2 + (mi & 1)) ^ (nl & 7);
                int ul = (4 + ks * 2 + (mi & 1)) ^ (nl & 7);
                ldm_x4(bh[2*jp][0], bh[2*jp][1], bh[2*jp+1][0], bh[2*jp+1][1],
                       Bb + nl * 128 + uh * 16);
                ldm_x4(bl[2*jp][0], bl[2*jp][1], bl[2*jp+1][0], bl[2*jp+1][1],
                       Bb + nl * 128 + ul * 16);
            }
#pragma unroll
            for (int i = 0; i < 4; i++) {
                int ml = wm * 64 + i * 16 + (mi & 1) * 8 + r8;
                int uh = (    ks * 2 + (mi >> 1)) ^ (ml & 7);
                int ul = (4 + ks * 2 + (mi >> 1)) ^ (ml & 7);
                unsigned ah[4], al[4];
                ldm_x4(ah[0], ah[1], ah[2], ah[3], Ab + ml * 128 + uh * 16);
                ldm_x4(al[0], al[1], al[2], al[3], Ab + ml * 128 + ul * 16);
#pragma unroll
                for (int j = 0; j < 4; j++) {
                    mma16816(acc[i][j], ah, bh[j]);
                    mma16816(acc[i][j], ah, bl[j]);
                    mma16816(acc[i][j], al, bh[j]);
                }
            }
        }
        __syncthreads();
        if (c + 2 < nch) stage((c + 2) * 32, c & 1);
    }

    const int g = l >> 2, t = l & 3;
#pragma unroll
    for (int i = 0; i < 4; i++) {
        size_t row = m0 + wm * 64 + i * 16 + g;
#pragma unroll
        for (int j = 0; j < 4; j++) {
            size_t col = n0 + wn * 32 + j * 8 + t * 2;
            if (!SPLITOUT) {
                *(float2*)&Cf[row * ldc + col] =
                    make_float2(acc[i][j][0] * scale, acc[i][j][1] * scale);
                *(float2*)&Cf[(row + 8) * ldc + col] =
                    make_float2(acc[i][j][2] * scale, acc[i][j][3] * scale);
            } else {
                bf16 h0, l0, h1, l1;
                split1(acc[i][j][0] * scale, h0, l0);
                split1(acc[i][j][1] * scale, h1, l1);
                *(unsigned*)&Ch[row * ldc + col] = pack2(h0, h1);
                *(unsigned*)&Cl[row * ldc + col] = pack2(l0, l1);
                split1(acc[i][j][2] * scale, h0, l0);
                split1(acc[i][j][3] * scale, h1, l1);
                *(unsigned*)&Ch[(row + 8) * ldc + col] = pack2(h0, h1);
                *(unsigned*)&Cl[(row + 8) * ldc + col] = pack2(l0, l1);
            }
        }
    }
}

// ---------------------------------------------------------------------------
// MERGED projection kernel: qproj (256) + kproj (32) + vprojT (32) = 320 CTAs
// ---------------------------------------------------------------------------
__global__ __launch_bounds__(256, 2) void k_proj3() {
    int idx = blockIdx.x;
    if (idx < 256) {
        int bx = idx & 15, by = idx >> 4;
        gemm_core<true, true>(g_Hh, g_Hl, H, g_QBh, g_QBl, H, 64,
                              by * 128, bx * 128, 1.f,
                              nullptr, g_Qh, g_Ql, H);
    } else if (idx < 288) {
        int i = idx - 256;
        int bx = i & 1, by = i >> 1;
        gemm_core<false, true>(g_Hh, g_Hl, H, g_KBh, g_KBl, H, 64,
                               by * 128, bx * 128, 1.f,
                               nullptr, g_Kh, g_Kl, ROOM);
    } else {
        int i = idx - 288;
        int bx = i & 15, by = i >> 4;
        gemm_core<false, true>(g_VBh, g_VBl, H, g_Hh, g_Hl, H, 64,
                               by * 128, bx * 128, 1.f,
                               nullptr, g_Vth, g_Vtl, S);
    }
}

// scores: compacted lower-triangular grid (136 tiles per head)
__global__ __launch_bounds__(256, 2) void k_scores(float* __restrict__ W) {
    const int h = blockIdx.y;
    int t = blockIdx.x;                         // 0..135
    int by = (int)((sqrtf(8.f * t + 1.f) - 1.f) * 0.5f);
    while ((by + 1) * (by + 2) / 2 <= t) by++;
    while (by * (by + 1) / 2 > t) by--;
    int bx = t - by * (by + 1) / 2;
    gemm_core<false, false>(g_Qh + h * HD, g_Ql + h * HD, H,
                            g_Kh + (h & 1) * HD, g_Kl + (h & 1) * HD, ROOM,
                            4, by * 128, bx * 128, SCALE,
                            W + (size_t)h * S * S, nullptr, nullptr, S);
}

// AV: A[q, h*128+d] = sum_k W[q,k] Vt[d,k]   (K causally limited)
__global__ __launch_bounds__(256, 2) void k_av() {
    const int h = blockIdx.z, by = blockIdx.y;
    gemm_core<false, true>(g_Wh + (size_t)h * S * S, g_Wl + (size_t)h * S * S, S,
                           g_Vth + (size_t)(h & 1) * 128 * S,
                           g_Vtl + (size_t)(h & 1) * 128 * S, S,
                           (by + 1) * 4, by * 128, 0, 1.f,
                           nullptr, g_Ah + h * HD, g_Al + h * HD, H);
}
__global__ __launch_bounds__(256, 2) void k_oproj(float* __restrict__ out) {
    gemm_core<false, false>(g_Ah, g_Al, H, g_OBth, g_OBtl, H, 64,
                            blockIdx.y * 128, blockIdx.x * 128, 1.f,
                            out, nullptr, nullptr, H);
}

// ---------------------------------------------------------------------------
// Pre-convert kernels
// ---------------------------------------------------------------------------
__global__ void normalize_rooms_kernel(const int* __restrict__ w) {
    bool is64 = (w[1] == 0) && (w[3] == 0) && (w[5] == 0) && (w[7] == 0);
    for (int i = 0; i < 8; i++)
        g_rooms[i] = is64 ? w[2 * i] : w[i];
}

#define N4_H   (S * H / 4)
#define N4_QB  (H * H / 4)
#define N4_KB  (ROOM * H / 4)
#define N4_ALL (N4_H + N4_QB + 2 * N4_KB)

__global__ __launch_bounds__(256) void conv_all(
    const float* __restrict__ hidden, const float* __restrict__ qb,
    const float* __restrict__ kb, const float* __restrict__ vb)
{
    int i = blockIdx.x * 256 + threadIdx.x;
    if (i >= N4_ALL) return;
    const float* src;
    bf16 *dh, *dl;
    int o = i;
    if (o < N4_H)                 { src = hidden; dh = g_Hh;  dl = g_Hl;  }
    else if ((o -= N4_H) < N4_QB) { src = qb;     dh = g_QBh; dl = g_QBl; }
    else if ((o -= N4_QB) < N4_KB){ src = kb;     dh = g_KBh; dl = g_KBl; }
    else          { o -= N4_KB;     src = vb;     dh = g_VBh; dl = g_VBl; }
    float4 v = ((const float4*)src)[o];
    bf16 h0, l0, h1, l1, h2, l2, h3, l3;
    split1(v.x, h0, l0); split1(v.y, h1, l1); split1(v.z, h2, l2); split1(v.w, h3, l3);
    ((uint2*)dh)[o] = make_uint2(pack2(h0, h1), pack2(h2, h3));
    ((uint2*)dl)[o] = make_uint2(pack2(l0, l1), pack2(l2, l3));
}

// transpose + gather: OBt[n][t] = ob[rooms[t>>8]*256 + (t&255)][n]
__global__ void conv_obt(const float* __restrict__ ob) {
    __shared__ float s[32][33];
    int t0 = blockIdx.y * 32, n0v = blockIdx.x * 32;
    int tx = threadIdx.x, ty = threadIdx.y;   // (32, 8)
#pragma unroll
    for (int i = 0; i < 4; i++) {
        int r = ty + i * 8;
        int sr = g_rooms[(t0 + r) >> 8] * ROOM + ((t0 + r) & 255);
        s[r][tx] = ob[(size_t)sr * H + n0v + tx];
    }
    __syncthreads();
#pragma unroll
    for (int i = 0; i < 4; i++) {
        int r = ty + i * 8;
        float v = s[tx][r];
        bf16 h, l;
        split1(v, h, l);
        g_OBth[(size_t)(n0v + r) * H + t0 + tx] = h;
        g_OBtl[(size_t)(n0v + r) * H + t0 + tx] = l;
    }
}

// ---------------------------------------------------------------------------
// Softmax per (head, q-row): one read; writes fp32 W (full row) + bf16 hi/lo
// planes zero-filled to the q-block boundary.
// ---------------------------------------------------------------------------
__global__ __launch_bounds__(256) void softmax_kernel(float* __restrict__ W) {
    const int q = blockIdx.x, h = blockIdx.y;
    float* row = W + ((size_t)h * S + q) * S;
    unsigned* rh = (unsigned*)(g_Wh + ((size_t)h * S + q) * S);
    unsigned* rl = (unsigned*)(g_Wl + ((size_t)h * S + q) * S);
    const int L = q + 1;
    const int Lpad = ((q >> 7) + 1) << 7;
    const int tid = threadIdx.x;
    __shared__ float sh[8];

    float2 v[4];
    float m = -3.4e38f;
#pragma unroll
    for (int i = 0; i < 4; i++) {
        int p = tid + i * 256;
        float2 x = ((const float2*)row)[p];
        int k0 = p * 2;
        v[i].x = (k0     < L) ? x.x : -3.4e38f;
        v[i].y = (k0 + 1 < L) ? x.y : -3.4e38f;
        m = fmaxf(m, fmaxf(v[i].x, v[i].y));
    }
#pragma unroll
    for (int o = 16; o > 0; o >>= 1) m = fmaxf(m, __shfl_xor_sync(0xffffffffu, m, o));
    if ((tid & 31) == 0) sh[tid >> 5] = m;
    __syncthreads();
    float mm = sh[0];
#pragma unroll
    for (int i = 1; i < 8; i++) mm = fmaxf(mm, sh[i]);
    __syncthreads();

    float ex[4], ey[4], ssum = 0.f;
#pragma unroll
    for (int i = 0; i < 4; i++) {
        int k0 = (tid + i * 256) * 2;
        ex[i] = (k0     < L) ? __expf(v[i].x - mm) : 0.f;
        ey[i] = (k0 + 1 < L) ? __expf(v[i].y - mm) : 0.f;
        ssum += ex[i] + ey[i];
    }
#pragma unroll
    for (int o = 16; o > 0; o >>= 1) ssum += __shfl_xor_sync(0xffffffffu, ssum, o);
    if ((tid & 31) == 0) sh[tid >> 5] = ssum;
    __syncthreads();
    float tot = 0.f;
#pragma unroll
    for (int i = 0; i < 8; i++) tot += sh[i];
    const float inv = 1.0f / tot;

#pragma unroll
    for (int i = 0; i < 4; i++) {
        int p = tid + i * 256;
        int k0 = p * 2;
        float wx = ex[i] * inv, wy = ey[i] * inv;
        ((float2*)row)[p] = make_float2(wx, wy);
        if (k0 < Lpad) {
            bf16 h0, l0, h1, l1;
            split1(wx, h0, l0); split1(wy, h1, l1);
            rh[p] = pack2(h0, h1);
            rl[p] = pack2(l0, l1);
        }
    }
}

// ---------------------------------------------------------------------------
// Launch
// ---------------------------------------------------------------------------
extern "C" void kernel_launch(void* const* d_in, const int* in_sizes, int n_in,
                              void* d_out, int out_size)
{
    const float* hidden = (const float*)d_in[0];
    const float* qb     = (const float*)d_in[1];
    const float* kb     = (const float*)d_in[2];
    const float* vb     = (const float*)d_in[3];
    const float* ob     = (const float*)d_in[4];
    const int*   rooms_raw = (const int*)d_in[5];

    float* out   = (float*)d_out;
    float* o_out = out;                      // [S, H]
    float* W     = out + (size_t)S * H;      // [NH, S, S]

    (void)in_sizes; (void)n_in; (void)out_size;

    cudaFuncSetAttribute(k_proj3,  cudaFuncAttributeMaxDynamicSharedMemorySize, DSMEM);
    cudaFuncSetAttribute(k_scores, cudaFuncAttributeMaxDynamicSharedMemorySize, DSMEM);
    cudaFuncSetAttribute(k_av,     cudaFuncAttributeMaxDynamicSharedMemorySize, DSMEM);
    cudaFuncSetAttribute(k_oproj,  cudaFuncAttributeMaxDynamicSharedMemorySize, DSMEM);

    // 0) canonicalize rooms + pre-split operands to bf16 hi/lo planes
    normalize_rooms_kernel<<<1, 1>>>(rooms_raw);
    conv_all<<<(N4_ALL + 255) / 256, 256>>>(hidden, qb, kb, vb);
    conv_obt<<<dim3(H / 32, H / 32), dim3(32, 8)>>>(ob);

    // 1) all three projections in one wave-filling launch
    k_proj3<<<320, 256, DSMEM>>>();

    // 2) scores (compacted lower-triangular grid)
    k_scores<<<dim3(136, NH), 256, DSMEM>>>(W);

    // 3) softmax (fp32 W + bf16 planes)
    softmax_kernel<<<dim3(S, NH), 256>>>(W);

    // 4) AV
    k_av<<<dim3(1, 16, NH), 256, DSMEM>>>();

    // 5) O projection
    k_oproj<<<dim3(16, 16), 256, DSMEM>>>(o_out);
}

// round 16
// speedup vs baseline: 1.1508x; 1.1508x over previous
#include <cuda_runtime.h>
#include <cuda_bf16.h>
#include <cstdint>
#include <math.h>

#define S   2048
#define H   2048
#define ROOM 256
#define NH  16
#define HD  128
#define SCALE 0.08838834764831845f  // 1/sqrt(128)

typedef __nv_bfloat16 bf16;

// ---------------- device globals (allocation-free scratch) ----------------
__device__ __align__(16) bf16 g_Hh [(size_t)S*H],    g_Hl [(size_t)S*H];     // hidden planes
__device__ __align__(16) bf16 g_QBh[(size_t)H*H],    g_QBl[(size_t)H*H];     // q_block planes
__device__ __align__(16) bf16 g_KBh[(size_t)ROOM*H], g_KBl[(size_t)ROOM*H];  // k_block planes
__device__ __align__(16) bf16 g_VBh[(size_t)ROOM*H], g_VBl[(size_t)ROOM*H];  // v_block planes
__device__ __align__(16) bf16 g_OBth[(size_t)H*H],   g_OBtl[(size_t)H*H];    // o_active^T [n][t]
__device__ __align__(16) bf16 g_Qh [(size_t)S*H],    g_Ql [(size_t)S*H];     // Q projection planes
__device__ __align__(16) bf16 g_Kh [(size_t)S*ROOM], g_Kl [(size_t)S*ROOM];  // k_one planes
__device__ __align__(16) bf16 g_Vth[(size_t)ROOM*S], g_Vtl[(size_t)ROOM*S];  // v_one^T [d][s]
__device__ __align__(16) bf16 g_Wh [(size_t)NH*S*S], g_Wl [(size_t)NH*S*S];  // softmaxed W planes
__device__ __align__(16) float g_A [(size_t)S*H];                            // attn_out fp32 (split-K accum)
__device__ __align__(16) bf16 g_Ah [(size_t)S*H],    g_Al [(size_t)S*H];     // attn_out planes
__device__ int g_rooms[8];

// ---------------- helpers ----------------
__device__ __forceinline__ uint32_t smem_u32(const void* p) {
    uint32_t a;
    asm("{ .reg .u64 t; cvta.to.shared.u64 t, %1; cvt.u32.u64 %0, t; }" : "=r"(a) : "l"(p));
    return a;
}
__device__ __forceinline__ void split1(float x, bf16& h, bf16& l) {
    h = __float2bfloat16_rn(x);
    l = __float2bfloat16_rn(x - __bfloat162float(h));
}
__device__ __forceinline__ unsigned pack2(bf16 a, bf16 b) {
    return ((unsigned)__bfloat16_as_ushort(b) << 16) | __bfloat16_as_ushort(a);
}
__device__ __forceinline__ void mma16816(float* d, const unsigned* a, const unsigned* b)
{
    asm volatile(
        "mma.sync.aligned.m16n8k16.row.col.f32.bf16.bf16.f32 "
        "{%0,%1,%2,%3}, {%4,%5,%6,%7}, {%8,%9}, {%0,%1,%2,%3};\n"
        : "+f"(d[0]), "+f"(d[1]), "+f"(d[2]), "+f"(d[3])
        : "r"(a[0]), "r"(a[1]), "r"(a[2]), "r"(a[3]), "r"(b[0]), "r"(b[1]));
}
__device__ __forceinline__ void ldm_x4(unsigned &r0, unsigned &r1, unsigned &r2, unsigned &r3,
                                       uint32_t addr)
{
    asm volatile("ldmatrix.sync.aligned.m8n8.x4.shared.b16 {%0,%1,%2,%3}, [%4];"
                 : "=r"(r0), "=r"(r1), "=r"(r2), "=r"(r3) : "r"(addr));
}
__device__ __forceinline__ void cpasync16(uint32_t dst, const void* src) {
    asm volatile("cp.async.cg.shared.global [%0], [%1], 16;" :: "r"(dst), "l"(src) : "memory");
}

// ---------------------------------------------------------------------------
// cp.async + ldmatrix NT GEMM core (round-12/14, proven).
// C[128,128] = A[M,K] @ B[N,K]^T, 3-term split (hh+hl+lh), fp32 accum.
// 128 threads, 4 warps (2x2 of 64x64), BK=32, double-buffered. Smem 64KB.
// OUTMODE: 0 = fp32 store, 1 = bf16 plane store, 2 = fp32 atomicAdd.
// ---------------------------------------------------------------------------
#define DSMEM (2 * 32768)

template<bool GATHER, int OUTMODE>
__device__ __forceinline__ void gemm_core(
    const bf16* __restrict__ Ah_, const bf16* __restrict__ Al_, int lda,
    const bf16* __restrict__ Bh_, const bf16* __restrict__ Bl_, int ldb,
    int nch, int m0, int n0, float scale,
    float* __restrict__ Cf, bf16* __restrict__ Ch, bf16* __restrict__ Cl, int ldc)
{
    extern __shared__ char smemraw[];
    const uint32_t sbase = smem_u32(smemraw);
    const int tid = threadIdx.x;
    const int l = tid & 31, w = tid >> 5;
    const int wm = w >> 1, wn = w & 1;

    const int plane = (tid >> 2) & 1;
    const int k8    = tid & 3;
    const int r0    = tid >> 3;
    const int swu   = (tid & 7) ^ (r0 & 7);
    const bf16* Asrc = (plane ? Al_ : Ah_) + (size_t)(m0 + r0) * lda + k8 * 8;
    int brow = n0 + r0;
    if (GATHER) brow = g_rooms[n0 >> 8] * ROOM + ((n0 + r0) & 255);
    const bf16* Bsrc = (plane ? Bl_ : Bh_) + (size_t)brow * ldb + k8 * 8;
    const uint32_t dA0 = sbase + r0 * 128 + swu * 16;
    const uint32_t dB0 = dA0 + 16384;

    auto stage = [&](int kk, int buf) {
        const uint32_t boff = buf * 32768;
        const bf16* as = Asrc + kk;
        const bf16* bs = Bsrc + kk;
#pragma unroll
        for (int i = 0; i < 8; i++) {
            cpasync16(dA0 + boff + i * 2048, as + (size_t)i * 16 * lda);
            cpasync16(dB0 + boff + i * 2048, bs + (size_t)i * 16 * ldb);
        }
        asm volatile("cp.async.commit_group;" ::: "memory");
    };

    float acc[4][8][4];
#pragma unroll
    for (int i = 0; i < 4; i++)
#pragma unroll
        for (int j = 0; j < 8; j++)
#pragma unroll
            for (int r = 0; r < 4; r++) acc[i][j][r] = 0.f;

    stage(0, 0);
    stage(32, 1);

    for (int c = 0; c < nch; c++) {
        if (c + 1 < nch) asm volatile("cp.async.wait_group 1;" ::: "memory");
        else             asm volatile("cp.async.wait_group 0;" ::: "memory");
        __syncthreads();
        const uint32_t Ab = sbase + (c & 1) * 32768;
        const uint32_t Bb = Ab + 16384;
        const int mi = l >> 3;
        const int r8 = l & 7;

#pragma unroll
        for (int ks = 0; ks < 2; ks++) {
            unsigned bh[8][2], bl[8][2];
#pragma unroll
            for (int jp = 0; jp < 4; jp++) {
                int nl = wn * 64 + jp * 16 + (mi >> 1) * 8 + r8;
                int uh = (    ks * 2 + (mi & 1)) ^ (nl & 7);
                int ul = (4 + ks * 2 + (mi & 1)) ^ (nl & 7);
                ldm_x4(bh[2*jp][0], bh[2*jp][1], bh[2*jp+1][0], bh[2*jp+1][1],
                       Bb + nl * 128 + uh * 16);
                ldm_x4(bl[2*jp][0], bl[2*jp][1], bl[2*jp+1][0], bl[2*jp+1][1],
                       Bb + nl * 128 + ul * 16);
            }
#pragma unroll
            for (int i = 0; i < 4; i++) {
                int ml = wm * 64 + i * 16 + (mi & 1) * 8 + r8;
                int uh = (    ks * 2 + (mi >> 1)) ^ (ml & 7);
                int ul = (4 + ks * 2 + (mi >> 1)) ^ (ml & 7);
                unsigned ah[4], al[4];
                ldm_x4(ah[0], ah[1], ah[2], ah[3], Ab + ml * 128 + uh * 16);
                ldm_x4(al[0], al[1], al[2], al[3], Ab + ml * 128 + ul * 16);
#pragma unroll
                for (int j = 0; j < 8; j++) {
                    mma16816(acc[i][j], ah, bh[j]);
                    mma16816(acc[i][j], ah, bl[j]);
                    mma16816(acc[i][j], al, bh[j]);
                }
            }
        }
        __syncthreads();
        if (c + 2 < nch) stage((c + 2) * 32, c & 1);
    }

    const int g = l >> 2, t = l & 3;
#pragma unroll
    for (int i = 0; i < 4; i++) {
        size_t row = m0 + wm * 64 + i * 16 + g;
#pragma unroll
        for (int j = 0; j < 8; j++) {
            size_t col = n0 + wn * 64 + j * 8 + t * 2;
            if (OUTMODE == 0) {
                *(float2*)&Cf[row * ldc + col] =
                    make_float2(acc[i][j][0] * scale, acc[i][j][1] * scale);
                *(float2*)&Cf[(row + 8) * ldc + col] =
                    make_float2(acc[i][j][2] * scale, acc[i][j][3] * scale);
            } else if (OUTMODE == 1) {
                bf16 h0, l0, h1, l1;
                split1(acc[i][j][0] * scale, h0, l0);
                split1(acc[i][j][1] * scale, h1, l1);
                *(unsigned*)&Ch[row * ldc + col] = pack2(h0, h1);
                *(unsigned*)&Cl[row * ldc + col] = pack2(l0, l1);
                split1(acc[i][j][2] * scale, h0, l0);
                split1(acc[i][j][3] * scale, h1, l1);
                *(unsigned*)&Ch[(row + 8) * ldc + col] = pack2(h0, h1);
                *(unsigned*)&Cl[(row + 8) * ldc + col] = pack2(l0, l1);
            } else {
                atomicAdd(&Cf[row * ldc + col],     acc[i][j][0]);
                atomicAdd(&Cf[row * ldc + col + 1], acc[i][j][1]);
                atomicAdd(&Cf[(row + 8) * ldc + col],     acc[i][j][2]);
                atomicAdd(&Cf[(row + 8) * ldc + col + 1], acc[i][j][3]);
            }
        }
    }
}

// ---------------------------------------------------------------------------
// MERGED projection kernel: qproj (256) + kproj (32) + vprojT (32) = 320 CTAs
// ---------------------------------------------------------------------------
__global__ __launch_bounds__(128, 2) void k_proj3() {
    int idx = blockIdx.x;
    if (idx < 256) {
        int bx = idx & 15, by = idx >> 4;
        gemm_core<true, 1>(g_Hh, g_Hl, H, g_QBh, g_QBl, H, 64,
                           by * 128, bx * 128, 1.f,
                           nullptr, g_Qh, g_Ql, H);
    } else if (idx < 288) {
        int i = idx - 256;
        int bx = i & 1, by = i >> 1;
        gemm_core<false, 1>(g_Hh, g_Hl, H, g_KBh, g_KBl, H, 64,
                            by * 128, bx * 128, 1.f,
                            nullptr, g_Kh, g_Kl, ROOM);
    } else {
        int i = idx - 288;
        int bx = i & 15, by = i >> 4;
        gemm_core<false, 1>(g_VBh, g_VBl, H, g_Hh, g_Hl, H, 64,
                            by * 128, bx * 128, 1.f,
                            nullptr, g_Vth, g_Vtl, S);
    }
}

// scores: compacted lower-triangular grid (136 tiles per head)
__global__ __launch_bounds__(128, 2) void k_scores(float* __restrict__ W) {
    const int h = blockIdx.y;
    int t = blockIdx.x;                         // 0..135
    int by = (int)((sqrtf(8.f * t + 1.f) - 1.f) * 0.5f);
    while ((by + 1) * (by + 2) / 2 <= t) by++;
    while (by * (by + 1) / 2 > t) by--;
    int bx = t - by * (by + 1) / 2;
    gemm_core<false, 0>(g_Qh + h * HD, g_Ql + h * HD, H,
                        g_Kh + (h & 1) * HD, g_Kl + (h & 1) * HD, ROOM,
                        4, by * 128, bx * 128, SCALE,
                        W + (size_t)h * S * S, nullptr, nullptr, S);
}

// AV split-K: tile (h, by) split into K-segments of <=8 chunks (2 q-blocks).
// pair index p (0..71) -> (by, seg). Partial sums atomicAdd into zeroed g_A.
__global__ __launch_bounds__(128, 2) void k_av() {
    const int h = blockIdx.z;
    int p = blockIdx.y, by = 0;
    for (by = 0; by < 16; by++) {
        int cnt = (by + 2) >> 1;            // ceil((by+1)/2)
        if (p < cnt) break;
        p -= cnt;
    }
    const int s = p;                        // K segment index
    const int nch_tot = (by + 1) * 4;
    int nch = nch_tot - s * 8;
    if (nch > 8) nch = 8;
    gemm_core<false, 2>(g_Wh + (size_t)h * S * S + s * 256,
                        g_Wl + (size_t)h * S * S + s * 256, S,
                        g_Vth + (size_t)(h & 1) * 128 * S + s * 256,
                        g_Vtl + (size_t)(h & 1) * 128 * S + s * 256, S,
                        nch, by * 128, 0, 1.f,
                        g_A + h * HD, nullptr, nullptr, H);
}

__global__ __launch_bounds__(128, 2) void k_oproj(float* __restrict__ out) {
    gemm_core<false, 0>(g_Ah, g_Al, H, g_OBth, g_OBtl, H, 64,
                        blockIdx.y * 128, blockIdx.x * 128, 1.f,
                        out, nullptr, nullptr, H);
}

// ---------------------------------------------------------------------------
// Pre/post-convert kernels
// ---------------------------------------------------------------------------
__global__ void normalize_rooms_kernel(const int* __restrict__ w) {
    bool is64 = (w[1] == 0) && (w[3] == 0) && (w[5] == 0) && (w[7] == 0);
    for (int i = 0; i < 8; i++)
        g_rooms[i] = is64 ? w[2 * i] : w[i];
}

#define N4_H   (S * H / 4)
#define N4_QB  (H * H / 4)
#define N4_KB  (ROOM * H / 4)
#define N4_ALL (N4_H + N4_QB + 2 * N4_KB)

__global__ __launch_bounds__(256) void conv_all(
    const float* __restrict__ hidden, const float* __restrict__ qb,
    const float* __restrict__ kb, const float* __restrict__ vb)
{
    int i = blockIdx.x * 256 + threadIdx.x;
    if (i >= N4_ALL) return;
    const float* src;
    bf16 *dh, *dl;
    int o = i;
    if (o < N4_H)                 { src = hidden; dh = g_Hh;  dl = g_Hl;  }
    else if ((o -= N4_H) < N4_QB) { src = qb;     dh = g_QBh; dl = g_QBl; }
    else if ((o -= N4_QB) < N4_KB){ src = kb;     dh = g_KBh; dl = g_KBl; }
    else          { o -= N4_KB;     src = vb;     dh = g_VBh; dl = g_VBl; }
    float4 v = ((const float4*)src)[o];
    bf16 h0, l0, h1, l1, h2, l2, h3, l3;
    split1(v.x, h0, l0); split1(v.y, h1, l1); split1(v.z, h2, l2); split1(v.w, h3, l3);
    ((uint2*)dh)[o] = make_uint2(pack2(h0, h1), pack2(h2, h3));
    ((uint2*)dl)[o] = make_uint2(pack2(l0, l1), pack2(l2, l3));
}

// zero g_A (split-K accumulator)
__global__ __launch_bounds__(256) void zero_A() {
    int i = blockIdx.x * 256 + threadIdx.x;
    ((float4*)g_A)[i] = make_float4(0.f, 0.f, 0.f, 0.f);
}

// g_A fp32 -> bf16 hi/lo planes
__global__ __launch_bounds__(256) void conv_A() {
    int i = blockIdx.x * 256 + threadIdx.x;
    float4 v = ((const float4*)g_A)[i];
    bf16 h0, l0, h1, l1, h2, l2, h3, l3;
    split1(v.x, h0, l0); split1(v.y, h1, l1); split1(v.z, h2, l2); split1(v.w, h3, l3);
    ((uint2*)g_Ah)[i] = make_uint2(pack2(h0, h1), pack2(h2, h3));
    ((uint2*)g_Al)[i] = make_uint2(pack2(l0, l1), pack2(l2, l3));
}

// transpose + gather: OBt[n][t] = ob[rooms[t>>8]*256 + (t&255)][n]
__global__ void conv_obt(const float* __restrict__ ob) {
    __shared__ float s[32][33];
    int t0 = blockIdx.y * 32, n0v = blockIdx.x * 32;
    int tx = threadIdx.x, ty = threadIdx.y;   // (32, 8)
#pragma unroll
    for (int i = 0; i < 4; i++) {
        int r = ty + i * 8;
        int sr = g_rooms[(t0 + r) >> 8] * ROOM + ((t0 + r) & 255);
        s[r][tx] = ob[(size_t)sr * H + n0v + tx];
    }
    __syncthreads();
#pragma unroll
    for (int i = 0; i < 4; i++) {
        int r = ty + i * 8;
        float v = s[tx][r];
        bf16 h, l;
        split1(v, h, l);
        g_OBth[(size_t)(n0v + r) * H + t0 + tx] = h;
        g_OBtl[(size_t)(n0v + r) * H + t0 + tx] = l;
    }
}

// ---------------------------------------------------------------------------
// Softmax per (head, q-row): one read; writes fp32 W (full row) + bf16 hi/lo
// planes zero-filled to the q-block boundary.
// ---------------------------------------------------------------------------
__global__ __launch_bounds__(256) void softmax_kernel(float* __restrict__ W) {
    const int q = blockIdx.x, h = blockIdx.y;
    float* row = W + ((size_t)h * S + q) * S;
    unsigned* rh = (unsigned*)(g_Wh + ((size_t)h * S + q) * S);
    unsigned* rl = (unsigned*)(g_Wl + ((size_t)h * S + q) * S);
    const int L = q + 1;
    const int Lpad = ((q >> 7) + 1) << 7;
    const int tid = threadIdx.x;
    __shared__ float sh[8];

    float2 v[4];
    float m = -3.4e38f;
#pragma unroll
    for (int i = 0; i < 4; i++) {
        int p = tid + i * 256;
        float2 x = ((const float2*)row)[p];
        int k0 = p * 2;
        v[i].x = (k0     < L) ? x.x : -3.4e38f;
        v[i].y = (k0 + 1 < L) ? x.y : -3.4e38f;
        m = fmaxf(m, fmaxf(v[i].x, v[i].y));
    }
#pragma unroll
    for (int o = 16; o > 0; o >>= 1) m = fmaxf(m, __shfl_xor_sync(0xffffffffu, m, o));
    if ((tid & 31) == 0) sh[tid >> 5] = m;
    __syncthreads();
    float mm = sh[0];
#pragma unroll
    for (int i = 1; i < 8; i++) mm = fmaxf(mm, sh[i]);
    __syncthreads();

    float ex[4], ey[4], ssum = 0.f;
#pragma unroll
    for (int i = 0; i < 4; i++) {
        int k0 = (tid + i * 256) * 2;
        ex[i] = (k0     < L) ? __expf(v[i].x - mm) : 0.f;
        ey[i] = (k0 + 1 < L) ? __expf(v[i].y - mm) : 0.f;
        ssum += ex[i] + ey[i];
    }
#pragma unroll
    for (int o = 16; o > 0; o >>= 1) ssum += __shfl_xor_sync(0xffffffffu, ssum, o);
    if ((tid & 31) == 0) sh[tid >> 5] = ssum;
    __syncthreads();
    float tot = 0.f;
#pragma unroll
    for (int i = 0; i < 8; i++) tot += sh[i];
    const float inv = 1.0f / tot;

#pragma unroll
    for (int i = 0; i < 4; i++) {
        int p = tid + i * 256;
        int k0 = p * 2;
        float wx = ex[i] * inv, wy = ey[i] * inv;
        ((float2*)row)[p] = make_float2(wx, wy);
        if (k0 < Lpad) {
            bf16 h0, l0, h1, l1;
            split1(wx, h0, l0); split1(wy, h1, l1);
            rh[p] = pack2(h0, h1);
            rl[p] = pack2(l0, l1);
        }
    }
}

// ---------------------------------------------------------------------------
// Launch
// ---------------------------------------------------------------------------
extern "C" void kernel_launch(void* const* d_in, const int* in_sizes, int n_in,
                              void* d_out, int out_size)
{
    const float* hidden = (const float*)d_in[0];
    const float* qb     = (const float*)d_in[1];
    const float* kb     = (const float*)d_in[2];
    const float* vb     = (const float*)d_in[3];
    const float* ob     = (const float*)d_in[4];
    const int*   rooms_raw = (const int*)d_in[5];

    float* out   = (float*)d_out;
    float* o_out = out;                      // [S, H]
    float* W     = out + (size_t)S * H;      // [NH, S, S]

    (void)in_sizes; (void)n_in; (void)out_size;

    cudaFuncSetAttribute(k_proj3,  cudaFuncAttributeMaxDynamicSharedMemorySize, DSMEM);
    cudaFuncSetAttribute(k_scores, cudaFuncAttributeMaxDynamicSharedMemorySize, DSMEM);
    cudaFuncSetAttribute(k_av,     cudaFuncAttributeMaxDynamicSharedMemorySize, DSMEM);
    cudaFuncSetAttribute(k_oproj,  cudaFuncAttributeMaxDynamicSharedMemorySize, DSMEM);

    // 0) canonicalize rooms + pre-split operands + zero split-K accumulator
    normalize_rooms_kernel<<<1, 1>>>(rooms_raw);
    conv_all<<<(N4_ALL + 255) / 256, 256>>>(hidden, qb, kb, vb);
    conv_obt<<<dim3(H / 32, H / 32), dim3(32, 8)>>>(ob);
    zero_A<<<(S * H / 4) / 256, 256>>>();

    // 1) all three projections in one wave-filling launch
    k_proj3<<<320, 128, DSMEM>>>();

    // 2) scores (compacted lower-triangular grid)
    k_scores<<<dim3(136, NH), 128, DSMEM>>>(W);

    // 3) softmax (fp32 W + bf16 planes)
    softmax_kernel<<<dim3(S, NH), 256>>>(W);

    // 4) AV (split-K, balanced, atomic accumulate)
    k_av<<<dim3(1, 72, NH), 128, DSMEM>>>();

    // 5) attn_out fp32 -> planes
    conv_A<<<(S * H / 4) / 256, 256>>>();

    // 6) O projection
    k_oproj<<<dim3(16, 16), 128, DSMEM>>>(o_out);
}

// round 17
// speedup vs baseline: 1.2254x; 1.0648x over previous
#include <cuda_runtime.h>
#include <cuda_bf16.h>
#include <cstdint>
#include <math.h>

#define S   2048
#define H   2048
#define ROOM 256
#define NH  16
#define HD  128
#define SCALE 0.08838834764831845f  // 1/sqrt(128)

typedef __nv_bfloat16 bf16;

// ---------------- device globals (allocation-free scratch) ----------------
__device__ __align__(16) bf16 g_Hh [(size_t)S*H],    g_Hl [(size_t)S*H];     // hidden planes
__device__ __align__(16) bf16 g_QBh[(size_t)H*H],    g_QBl[(size_t)H*H];     // q_block planes
__device__ __align__(16) bf16 g_KBh[(size_t)ROOM*H], g_KBl[(size_t)ROOM*H];  // k_block planes
__device__ __align__(16) bf16 g_VBh[(size_t)ROOM*H], g_VBl[(size_t)ROOM*H];  // v_block planes
__device__ __align__(16) bf16 g_OBth[(size_t)H*H],   g_OBtl[(size_t)H*H];    // o_active^T [n][t]
__device__ __align__(16) bf16 g_Qh [(size_t)S*H],    g_Ql [(size_t)S*H];     // Q projection planes
__device__ __align__(16) bf16 g_Kh [(size_t)S*ROOM], g_Kl [(size_t)S*ROOM];  // k_one planes
__device__ __align__(16) bf16 g_Vth[(size_t)ROOM*S], g_Vtl[(size_t)ROOM*S];  // v_one^T [d][s]
__device__ __align__(16) bf16 g_Wh [(size_t)NH*S*S], g_Wl [(size_t)NH*S*S];  // softmaxed W planes
__device__ __align__(16) float g_A [(size_t)S*H];                            // attn_out fp32 (split-K accum)
__device__ __align__(16) bf16 g_Ah [(size_t)S*H],    g_Al [(size_t)S*H];     // attn_out planes
__device__ __align__(16) float g_Qf [(size_t)S*H];                           // proj split-K accumulators
__device__ __align__(16) float g_Kf [(size_t)S*ROOM];
__device__ __align__(16) float g_Vtf[(size_t)ROOM*S];
__device__ int g_rooms[8];

// ---------------- helpers ----------------
__device__ __forceinline__ uint32_t smem_u32(const void* p) {
    uint32_t a;
    asm("{ .reg .u64 t; cvta.to.shared.u64 t, %1; cvt.u32.u64 %0, t; }" : "=r"(a) : "l"(p));
    return a;
}
__device__ __forceinline__ void split1(float x, bf16& h, bf16& l) {
    h = __float2bfloat16_rn(x);
    l = __float2bfloat16_rn(x - __bfloat162float(h));
}
__device__ __forceinline__ unsigned pack2(bf16 a, bf16 b) {
    return ((unsigned)__bfloat16_as_ushort(b) << 16) | __bfloat16_as_ushort(a);
}
__device__ __forceinline__ void mma16816(float* d, const unsigned* a, const unsigned* b)
{
    asm volatile(
        "mma.sync.aligned.m16n8k16.row.col.f32.bf16.bf16.f32 "
        "{%0,%1,%2,%3}, {%4,%5,%6,%7}, {%8,%9}, {%0,%1,%2,%3};\n"
        : "+f"(d[0]), "+f"(d[1]), "+f"(d[2]), "+f"(d[3])
        : "r"(a[0]), "r"(a[1]), "r"(a[2]), "r"(a[3]), "r"(b[0]), "r"(b[1]));
}
__device__ __forceinline__ void ldm_x4(unsigned &r0, unsigned &r1, unsigned &r2, unsigned &r3,
                                       uint32_t addr)
{
    asm volatile("ldmatrix.sync.aligned.m8n8.x4.shared.b16 {%0,%1,%2,%3}, [%4];"
                 : "=r"(r0), "=r"(r1), "=r"(r2), "=r"(r3) : "r"(addr));
}
__device__ __forceinline__ void cpasync16(uint32_t dst, const void* src) {
    asm volatile("cp.async.cg.shared.global [%0], [%1], 16;" :: "r"(dst), "l"(src) : "memory");
}

// ---------------------------------------------------------------------------
// cp.async + ldmatrix NT GEMM core (round-12/14, proven).
// C[128,128] = A[M,K] @ B[N,K]^T, 3-term split (hh+hl+lh), fp32 accum.
// 128 threads, 4 warps (2x2 of 64x64), BK=32, double-buffered. Smem 64KB.
// OUTMODE: 0 = fp32 store, 1 = bf16 plane store, 2 = fp32 atomicAdd.
// ---------------------------------------------------------------------------
#define DSMEM (2 * 32768)

template<bool GATHER, int OUTMODE>
__device__ __forceinline__ void gemm_core(
    const bf16* __restrict__ Ah_, const bf16* __restrict__ Al_, int lda,
    const bf16* __restrict__ Bh_, const bf16* __restrict__ Bl_, int ldb,
    int nch, int m0, int n0, float scale,
    float* __restrict__ Cf, bf16* __restrict__ Ch, bf16* __restrict__ Cl, int ldc)
{
    extern __shared__ char smemraw[];
    const uint32_t sbase = smem_u32(smemraw);
    const int tid = threadIdx.x;
    const int l = tid & 31, w = tid >> 5;
    const int wm = w >> 1, wn = w & 1;

    const int plane = (tid >> 2) & 1;
    const int k8    = tid & 3;
    const int r0    = tid >> 3;
    const int swu   = (tid & 7) ^ (r0 & 7);
    const bf16* Asrc = (plane ? Al_ : Ah_) + (size_t)(m0 + r0) * lda + k8 * 8;
    int brow = n0 + r0;
    if (GATHER) brow = g_rooms[n0 >> 8] * ROOM + ((n0 + r0) & 255);
    const bf16* Bsrc = (plane ? Bl_ : Bh_) + (size_t)brow * ldb + k8 * 8;
    const uint32_t dA0 = sbase + r0 * 128 + swu * 16;
    const uint32_t dB0 = dA0 + 16384;

    auto stage = [&](int kk, int buf) {
        const uint32_t boff = buf * 32768;
        const bf16* as = Asrc + kk;
        const bf16* bs = Bsrc + kk;
#pragma unroll
        for (int i = 0; i < 8; i++) {
            cpasync16(dA0 + boff + i * 2048, as + (size_t)i * 16 * lda);
            cpasync16(dB0 + boff + i * 2048, bs + (size_t)i * 16 * ldb);
        }
        asm volatile("cp.async.commit_group;" ::: "memory");
    };

    float acc[4][8][4];
#pragma unroll
    for (int i = 0; i < 4; i++)
#pragma unroll
        for (int j = 0; j < 8; j++)
#pragma unroll
            for (int r = 0; r < 4; r++) acc[i][j][r] = 0.f;

    stage(0, 0);
    stage(32, 1);

    for (int c = 0; c < nch; c++) {
        if (c + 1 < nch) asm volatile("cp.async.wait_group 1;" ::: "memory");
        else             asm volatile("cp.async.wait_group 0;" ::: "memory");
        __syncthreads();
        const uint32_t Ab = sbase + (c & 1) * 32768;
        const uint32_t Bb = Ab + 16384;
        const int mi = l >> 3;
        const int r8 = l & 7;

#pragma unroll
        for (int ks = 0; ks < 2; ks++) {
            unsigned bh[8][2], bl[8][2];
#pragma unroll
            for (int jp = 0; jp < 4; jp++) {
                int nl = wn * 64 + jp * 16 + (mi >> 1) * 8 + r8;
                int uh = (    ks * 2 + (mi & 1)) ^ (nl & 7);
                int ul = (4 + ks * 2 + (mi & 1)) ^ (nl & 7);
                ldm_x4(bh[2*jp][0], bh[2*jp][1], bh[2*jp+1][0], bh[2*jp+1][1],
                       Bb + nl * 128 + uh * 16);
                ldm_x4(bl[2*jp][0], bl[2*jp][1], bl[2*jp+1][0], bl[2*jp+1][1],
                       Bb + nl * 128 + ul * 16);
            }
#pragma unroll
            for (int i = 0; i < 4; i++) {
                int ml = wm * 64 + i * 16 + (mi & 1) * 8 + r8;
                int uh = (    ks * 2 + (mi >> 1)) ^ (ml & 7);
                int ul = (4 + ks * 2 + (mi >> 1)) ^ (ml & 7);
                unsigned ah[4], al[4];
                ldm_x4(ah[0], ah[1], ah[2], ah[3], Ab + ml * 128 + uh * 16);
                ldm_x4(al[0], al[1], al[2], al[3], Ab + ml * 128 + ul * 16);
#pragma unroll
                for (int j = 0; j < 8; j++) {
                    mma16816(acc[i][j], ah, bh[j]);
                    mma16816(acc[i][j], ah, bl[j]);
                    mma16816(acc[i][j], al, bh[j]);
                }
            }
        }
        __syncthreads();
        if (c + 2 < nch) stage((c + 2) * 32, c & 1);
    }

    const int g = l >> 2, t = l & 3;
#pragma unroll
    for (int i = 0; i < 4; i++) {
        size_t row = m0 + wm * 64 + i * 16 + g;
#pragma unroll
        for (int j = 0; j < 8; j++) {
            size_t col = n0 + wn * 64 + j * 8 + t * 2;
            if (OUTMODE == 0) {
                *(float2*)&Cf[row * ldc + col] =
                    make_float2(acc[i][j][0] * scale, acc[i][j][1] * scale);
                *(float2*)&Cf[(row + 8) * ldc + col] =
                    make_float2(acc[i][j][2] * scale, acc[i][j][3] * scale);
            } else if (OUTMODE == 1) {
                bf16 h0, l0, h1, l1;
                split1(acc[i][j][0] * scale, h0, l0);
                split1(acc[i][j][1] * scale, h1, l1);
                *(unsigned*)&Ch[row * ldc + col] = pack2(h0, h1);
                *(unsigned*)&Cl[row * ldc + col] = pack2(l0, l1);
                split1(acc[i][j][2] * scale, h0, l0);
                split1(acc[i][j][3] * scale, h1, l1);
                *(unsigned*)&Ch[(row + 8) * ldc + col] = pack2(h0, h1);
                *(unsigned*)&Cl[(row + 8) * ldc + col] = pack2(l0, l1);
            } else {
                atomicAdd(&Cf[row * ldc + col],     acc[i][j][0]);
                atomicAdd(&Cf[row * ldc + col + 1], acc[i][j][1]);
                atomicAdd(&Cf[(row + 8) * ldc + col],     acc[i][j][2]);
                atomicAdd(&Cf[(row + 8) * ldc + col + 1], acc[i][j][3]);
            }
        }
    }
}

// ---------------------------------------------------------------------------
// Split-K projections: 320 tiles x 4 K-segments (16 chunks each) = 1280 CTAs.
// Accumulate into zeroed fp32 buffers via atomicAdd; conv_P builds planes.
// ---------------------------------------------------------------------------
__global__ __launch_bounds__(128, 2) void k_proj3() {
    int idx = blockIdx.x >> 2;
    int seg = blockIdx.x & 3;
    int koff = seg * 512;                // 16 chunks * 32
    if (idx < 256) {
        int bx = idx & 15, by = idx >> 4;
        gemm_core<true, 2>(g_Hh + koff, g_Hl + koff, H,
                           g_QBh + koff, g_QBl + koff, H, 16,
                           by * 128, bx * 128, 1.f,
                           g_Qf, nullptr, nullptr, H);
    } else if (idx < 288) {
        int i = idx - 256;
        int bx = i & 1, by = i >> 1;
        gemm_core<false, 2>(g_Hh + koff, g_Hl + koff, H,
                            g_KBh + koff, g_KBl + koff, H, 16,
                            by * 128, bx * 128, 1.f,
                            g_Kf, nullptr, nullptr, ROOM);
    } else {
        int i = idx - 288;
        int bx = i & 15, by = i >> 4;
        gemm_core<false, 2>(g_VBh + koff, g_VBl + koff, H,
                            g_Hh + koff, g_Hl + koff, H, 16,
                            by * 128, bx * 128, 1.f,
                            g_Vtf, nullptr, nullptr, S);
    }
}

// scores: compacted lower-triangular grid (136 tiles per head)
__global__ __launch_bounds__(128, 2) void k_scores(float* __restrict__ W) {
    const int h = blockIdx.y;
    int t = blockIdx.x;                         // 0..135
    int by = (int)((sqrtf(8.f * t + 1.f) - 1.f) * 0.5f);
    while ((by + 1) * (by + 2) / 2 <= t) by++;
    while (by * (by + 1) / 2 > t) by--;
    int bx = t - by * (by + 1) / 2;
    gemm_core<false, 0>(g_Qh + h * HD, g_Ql + h * HD, H,
                        g_Kh + (h & 1) * HD, g_Kl + (h & 1) * HD, ROOM,
                        4, by * 128, bx * 128, SCALE,
                        W + (size_t)h * S * S, nullptr, nullptr, S);
}

// AV split-K: tile (h, by) split into K-segments of <=8 chunks.
__global__ __launch_bounds__(128, 2) void k_av() {
    const int h = blockIdx.z;
    int p = blockIdx.y, by = 0;
    for (by = 0; by < 16; by++) {
        int cnt = (by + 2) >> 1;
        if (p < cnt) break;
        p -= cnt;
    }
    const int s = p;
    const int nch_tot = (by + 1) * 4;
    int nch = nch_tot - s * 8;
    if (nch > 8) nch = 8;
    gemm_core<false, 2>(g_Wh + (size_t)h * S * S + s * 256,
                        g_Wl + (size_t)h * S * S + s * 256, S,
                        g_Vth + (size_t)(h & 1) * 128 * S + s * 256,
                        g_Vtl + (size_t)(h & 1) * 128 * S + s * 256, S,
                        nch, by * 128, 0, 1.f,
                        g_A + h * HD, nullptr, nullptr, H);
}

__global__ __launch_bounds__(128, 2) void k_oproj(float* __restrict__ out) {
    gemm_core<false, 0>(g_Ah, g_Al, H, g_OBth, g_OBtl, H, 64,
                        blockIdx.y * 128, blockIdx.x * 128, 1.f,
                        out, nullptr, nullptr, H);
}

// ---------------------------------------------------------------------------
// Pre/post-convert kernels
// ---------------------------------------------------------------------------
__global__ void normalize_rooms_kernel(const int* __restrict__ w) {
    bool is64 = (w[1] == 0) && (w[3] == 0) && (w[5] == 0) && (w[7] == 0);
    for (int i = 0; i < 8; i++)
        g_rooms[i] = is64 ? w[2 * i] : w[i];
}

#define N4_H   (S * H / 4)
#define N4_QB  (H * H / 4)
#define N4_KB  (ROOM * H / 4)
#define N4_ALL (N4_H + N4_QB + 2 * N4_KB)

__global__ __launch_bounds__(256) void conv_all(
    const float* __restrict__ hidden, const float* __restrict__ qb,
    const float* __restrict__ kb, const float* __restrict__ vb)
{
    int i = blockIdx.x * 256 + threadIdx.x;
    if (i >= N4_ALL) return;
    const float* src;
    bf16 *dh, *dl;
    int o = i;
    if (o < N4_H)                 { src = hidden; dh = g_Hh;  dl = g_Hl;  }
    else if ((o -= N4_H) < N4_QB) { src = qb;     dh = g_QBh; dl = g_QBl; }
    else if ((o -= N4_QB) < N4_KB){ src = kb;     dh = g_KBh; dl = g_KBl; }
    else          { o -= N4_KB;     src = vb;     dh = g_VBh; dl = g_VBl; }
    float4 v = ((const float4*)src)[o];
    bf16 h0, l0, h1, l1, h2, l2, h3, l3;
    split1(v.x, h0, l0); split1(v.y, h1, l1); split1(v.z, h2, l2); split1(v.w, h3, l3);
    ((uint2*)dh)[o] = make_uint2(pack2(h0, h1), pack2(h2, h3));
    ((uint2*)dl)[o] = make_uint2(pack2(l0, l1), pack2(l2, l3));
}

// zero all split-K accumulators: g_Qf + g_Kf + g_Vtf + g_A
#define N4_Q  (S * H / 4)
#define N4_K2 (S * ROOM / 4)
#define N4_Z  (N4_Q + 2 * N4_K2 + N4_Q)
__global__ __launch_bounds__(256) void zero_scratch() {
    int i = blockIdx.x * 256 + threadIdx.x;
    if (i >= N4_Z) return;
    float4 z = make_float4(0.f, 0.f, 0.f, 0.f);
    int o = i;
    if (o < N4_Q)                  { ((float4*)g_Qf)[o] = z; }
    else if ((o -= N4_Q) < N4_K2)  { ((float4*)g_Kf)[o] = z; }
    else if ((o -= N4_K2) < N4_K2) { ((float4*)g_Vtf)[o] = z; }
    else           { o -= N4_K2;     ((float4*)g_A)[o] = z; }
}

// proj accumulators fp32 -> bf16 planes
#define N4_P (N4_Q + 2 * N4_K2)
__global__ __launch_bounds__(256) void conv_P() {
    int i = blockIdx.x * 256 + threadIdx.x;
    if (i >= N4_P) return;
    const float* src;
    bf16 *dh, *dl;
    int o = i;
    if (o < N4_Q)                 { src = g_Qf;  dh = g_Qh;  dl = g_Ql;  }
    else if ((o -= N4_Q) < N4_K2) { src = g_Kf;  dh = g_Kh;  dl = g_Kl;  }
    else          { o -= N4_K2;     src = g_Vtf; dh = g_Vth; dl = g_Vtl; }
    float4 v = ((const float4*)src)[o];
    bf16 h0, l0, h1, l1, h2, l2, h3, l3;
    split1(v.x, h0, l0); split1(v.y, h1, l1); split1(v.z, h2, l2); split1(v.w, h3, l3);
    ((uint2*)dh)[o] = make_uint2(pack2(h0, h1), pack2(h2, h3));
    ((uint2*)dl)[o] = make_uint2(pack2(l0, l1), pack2(l2, l3));
}

// g_A fp32 -> bf16 hi/lo planes
__global__ __launch_bounds__(256) void conv_A() {
    int i = blockIdx.x * 256 + threadIdx.x;
    float4 v = ((const float4*)g_A)[i];
    bf16 h0, l0, h1, l1, h2, l2, h3, l3;
    split1(v.x, h0, l0); split1(v.y, h1, l1); split1(v.z, h2, l2); split1(v.w, h3, l3);
    ((uint2*)g_Ah)[i] = make_uint2(pack2(h0, h1), pack2(h2, h3));
    ((uint2*)g_Al)[i] = make_uint2(pack2(l0, l1), pack2(l2, l3));
}

// transpose + gather: OBt[n][t] = ob[rooms[t>>8]*256 + (t&255)][n]
__global__ void conv_obt(const float* __restrict__ ob) {
    __shared__ float s[32][33];
    int t0 = blockIdx.y * 32, n0v = blockIdx.x * 32;
    int tx = threadIdx.x, ty = threadIdx.y;   // (32, 8)
#pragma unroll
    for (int i = 0; i < 4; i++) {
        int r = ty + i * 8;
        int sr = g_rooms[(t0 + r) >> 8] * ROOM + ((t0 + r) & 255);
        s[r][tx] = ob[(size_t)sr * H + n0v + tx];
    }
    __syncthreads();
#pragma unroll
    for (int i = 0; i < 4; i++) {
        int r = ty + i * 8;
        float v = s[tx][r];
        bf16 h, l;
        split1(v, h, l);
        g_OBth[(size_t)(n0v + r) * H + t0 + tx] = h;
        g_OBtl[(size_t)(n0v + r) * H + t0 + tx] = l;
    }
}

// ---------------------------------------------------------------------------
// Softmax per (head, q-row): one read; writes fp32 W (full row) + bf16 hi/lo
// planes zero-filled to the q-block boundary.
// ---------------------------------------------------------------------------
__global__ __launch_bounds__(256) void softmax_kernel(float* __restrict__ W) {
    const int q = blockIdx.x, h = blockIdx.y;
    float* row = W + ((size_t)h * S + q) * S;
    unsigned* rh = (unsigned*)(g_Wh + ((size_t)h * S + q) * S);
    unsigned* rl = (unsigned*)(g_Wl + ((size_t)h * S + q) * S);
    const int L = q + 1;
    const int Lpad = ((q >> 7) + 1) << 7;
    const int tid = threadIdx.x;
    __shared__ float sh[8];

    float2 v[4];
    float m = -3.4e38f;
#pragma unroll
    for (int i = 0; i < 4; i++) {
        int p = tid + i * 256;
        float2 x = ((const float2*)row)[p];
        int k0 = p * 2;
        v[i].x = (k0     < L) ? x.x : -3.4e38f;
        v[i].y = (k0 + 1 < L) ? x.y : -3.4e38f;
        m = fmaxf(m, fmaxf(v[i].x, v[i].y));
    }
#pragma unroll
    for (int o = 16; o > 0; o >>= 1) m = fmaxf(m, __shfl_xor_sync(0xffffffffu, m, o));
    if ((tid & 31) == 0) sh[tid >> 5] = m;
    __syncthreads();
    float mm = sh[0];
#pragma unroll
    for (int i = 1; i < 8; i++) mm = fmaxf(mm, sh[i]);
    __syncthreads();

    float ex[4], ey[4], ssum = 0.f;
#pragma unroll
    for (int i = 0; i < 4; i++) {
        int k0 = (tid + i * 256) * 2;
        ex[i] = (k0     < L) ? __expf(v[i].x - mm) : 0.f;
        ey[i] = (k0 + 1 < L) ? __expf(v[i].y - mm) : 0.f;
        ssum += ex[i] + ey[i];
    }
#pragma unroll
    for (int o = 16; o > 0; o >>= 1) ssum += __shfl_xor_sync(0xffffffffu, ssum, o);
    if ((tid & 31) == 0) sh[tid >> 5] = ssum;
    __syncthreads();
    float tot = 0.f;
#pragma unroll
    for (int i = 0; i < 8; i++) tot += sh[i];
    const float inv = 1.0f / tot;

#pragma unroll
    for (int i = 0; i < 4; i++) {
        int p = tid + i * 256;
        int k0 = p * 2;
        float wx = ex[i] * inv, wy = ey[i] * inv;
        ((float2*)row)[p] = make_float2(wx, wy);
        if (k0 < Lpad) {
            bf16 h0, l0, h1, l1;
            split1(wx, h0, l0); split1(wy, h1, l1);
            rh[p] = pack2(h0, h1);
            rl[p] = pack2(l0, l1);
        }
    }
}

// ---------------------------------------------------------------------------
// Launch
// ---------------------------------------------------------------------------
extern "C" void kernel_launch(void* const* d_in, const int* in_sizes, int n_in,
                              void* d_out, int out_size)
{
    const float* hidden = (const float*)d_in[0];
    const float* qb     = (const float*)d_in[1];
    const float* kb     = (const float*)d_in[2];
    const float* vb     = (const float*)d_in[3];
    const float* ob     = (const float*)d_in[4];
    const int*   rooms_raw = (const int*)d_in[5];

    float* out   = (float*)d_out;
    float* o_out = out;                      // [S, H]
    float* W     = out + (size_t)S * H;      // [NH, S, S]

    (void)in_sizes; (void)n_in; (void)out_size;

    cudaFuncSetAttribute(k_proj3,  cudaFuncAttributeMaxDynamicSharedMemorySize, DSMEM);
    cudaFuncSetAttribute(k_scores, cudaFuncAttributeMaxDynamicSharedMemorySize, DSMEM);
    cudaFuncSetAttribute(k_av,     cudaFuncAttributeMaxDynamicSharedMemorySize, DSMEM);
    cudaFuncSetAttribute(k_oproj,  cudaFuncAttributeMaxDynamicSharedMemorySize, DSMEM);

    // 0) canonicalize rooms + pre-split operands + zero split-K accumulators
    normalize_rooms_kernel<<<1, 1>>>(rooms_raw);
    conv_all<<<(N4_ALL + 255) / 256, 256>>>(hidden, qb, kb, vb);
    conv_obt<<<dim3(H / 32, H / 32), dim3(32, 8)>>>(ob);
    zero_scratch<<<(N4_Z + 255) / 256, 256>>>();

    // 1) projections: 320 tiles x 4 K-segments, atomic accumulate
    k_proj3<<<1280, 128, DSMEM>>>();
    conv_P<<<(N4_P + 255) / 256, 256>>>();

    // 2) scores (compacted lower-triangular grid)
    k_scores<<<dim3(136, NH), 128, DSMEM>>>(W);

    // 3) softmax (fp32 W + bf16 planes)
    softmax_kernel<<<dim3(S, NH), 256>>>(W);

    // 4) AV (split-K, balanced, atomic accumulate)
    k_av<<<dim3(1, 72, NH), 128, DSMEM>>>();

    // 5) attn_out fp32 -> planes
    conv_A<<<(S * H / 4) / 256, 256>>>();

    // 6) O projection
    k_oproj<<<dim3(16, 16), 128, DSMEM>>>(o_out);
}